// round 11
// baseline (speedup 1.0000x reference)
#include <cuda_runtime.h>

// ---------------- problem dims ----------------
#define Bsz   64
#define Tsz   512
#define Dsz   128
#define Hsz   512
#define HB    (Hsz * Bsz)        // 32768 floats per h buffer
#define NCTA  128
#define TPB   128
#define L0CTAS 64
#define KC    128                // k-chunk staged per inner pass
#define SMEM_BYTES ((512*24 + 512*24 + KC*Bsz) * 4)   // 49152+49152+32768 = 131072 B

typedef unsigned long long ull;

// ---------------- persistent device state (reset each launch where needed) ----------------
__device__ __align__(16) float g_xT[Tsz * Dsz * Bsz];   // X transposed to [t][d][b]  (16 MB)
__device__ __align__(16) float g_h1[2 * HB];            // layer0 hidden, double buffered, [k][b]
__device__ __align__(16) float g_h2[2 * HB];            // layer1 hidden, double buffered, [k][b]
__device__ unsigned g_flags[NCTA];                      // zero-init; reset to 0 at kernel end
__device__ unsigned g_release;                          // zero-init; reset to 0 at kernel end

// packed f32x2 FMA: full fp32 rate (plain 3-reg FFMA is half rate on sm_103a)
#define FMA2(acc, w, x) asm("fma.rn.f32x2 %0, %1, %2, %0;" : "+l"(acc) : "l"(w), "l"(x))

__device__ __forceinline__ void unpack2(ull v, float& lo, float& hi) {
    asm("mov.b64 {%0, %1}, %2;" : "=f"(lo), "=f"(hi) : "l"(v));
}

__device__ __forceinline__ float sigmoidf_(float x) {
    return __fdividef(1.0f, 1.0f + __expf(-x));
}
__device__ __forceinline__ float tanhf_(float x) {
    x = fminf(12.0f, fmaxf(-12.0f, x));
    float e = __expf(2.0f * x);
    return __fdividef(e - 1.0f, e + 1.0f);
}

// ---------------- grid barrier: distributed flags + CTA0 aggregation ----------------
// Requires all NCTA CTAs co-resident (grid=128 <= 148 SMs, 1 CTA/SM). val strictly increases.
__device__ __forceinline__ void gridbar(unsigned val, int cta, int tid) {
    __syncthreads();
    if (tid == 0) {
        __threadfence();                                   // make my writes visible first
        *((volatile unsigned*)&g_flags[cta]) = val;
    }
    if (cta == 0) {
        volatile unsigned* f = &g_flags[tid];              // TPB == NCTA: one flag per thread
        while (*f < val) __nanosleep(32);
        __syncthreads();
        if (tid == 0) {
            __threadfence();
            *((volatile unsigned*)&g_release) = val;
        }
    }
    if (tid == 0) {
        volatile unsigned* r = &g_release;
        while (*r < val) __nanosleep(32);
        __threadfence();                                   // acquire side
    }
    __syncthreads();
}

// ---------------- stage one KC x 64 chunk into SMEM (coalesced float4, L2 reads) ----------------
__device__ __forceinline__ void copy_chunk(float* stage, const float* __restrict__ src, int tid) {
    const float4* s = reinterpret_cast<const float4*>(src);
    float4* d = reinterpret_cast<float4*>(stage);
#pragma unroll
    for (int i = 0; i < (KC * Bsz / 4) / TPB; ++i)         // 16 iters
        d[tid + i * TPB] = __ldcg(s + tid + i * TPB);
}

// ---------------- inner accumulate over one KC chunk ----------------
// acc[j] packs gh[gu_base+2j][b] (lo) and gh[gu_base+2j+1][b] (hi) for this thread's batch col.
__device__ __forceinline__ void accum_phase(const float* __restrict__ Wsh,
                                            const float* __restrict__ stage,
                                            int k0, int col, int gu_base, ull acc[6]) {
#pragma unroll 4
    for (int kk = 0; kk < KC; ++kk) {
        float h = stage[kk * Bsz + col];
        ull hh; asm("mov.b64 %0, {%1, %1};" : "=l"(hh) : "f"(h));
        const ulonglong2* wp =
            reinterpret_cast<const ulonglong2*>(Wsh + (size_t)(k0 + kk) * 24 + gu_base);
        ulonglong2 w0 = wp[0];                              // LDS.128, warp-broadcast
        ulonglong2 w1 = wp[1];
        ulonglong2 w2 = wp[2];
        FMA2(acc[0], w0.x, hh); FMA2(acc[1], w0.y, hh);
        FMA2(acc[2], w1.x, hh); FMA2(acc[3], w1.y, hh);
        FMA2(acc[4], w2.x, hh); FMA2(acc[5], w2.y, hh);
    }
}

__global__ __launch_bounds__(TPB)
void gru_persistent(const float* __restrict__ X,
                    const float* __restrict__ W_ih0, const float* __restrict__ W_hh0,
                    const float* __restrict__ b_ih0, const float* __restrict__ b_hh0,
                    const float* __restrict__ W_ih1, const float* __restrict__ W_hh1,
                    const float* __restrict__ b_ih1, const float* __restrict__ b_hh1,
                    const float* __restrict__ W_fc,  const float* __restrict__ b_fc,
                    float* __restrict__ out) {
    extern __shared__ float smem[];
    float* WHs   = smem;                    // [512][24]  hh weights, gu = u*3+g inner
    float* WXs   = smem + 512 * 24;         // [Kx][24]   ih weights
    float* stage = smem + 2 * 512 * 24;     // [KC][64]   staged h/x chunk

    const int tid = threadIdx.x;
    const int cta = blockIdx.x;
    const int col = tid & 63;               // batch index this thread owns
    const int row = tid >> 6;               // 0/1: gate-unit half
    const int gu_base = row * 12;

    const bool role0 = (cta < L0CTAS);
    const int  lcta  = role0 ? cta : (cta - L0CTAS);
    const int  U0    = lcta * 8;            // global hidden-unit base for this CTA
    const int  Kx    = role0 ? Dsz : Hsz;

    const float* Whh = role0 ? W_hh0 : W_hh1;
    const float* Wih = role0 ? W_ih0 : W_ih1;
    const float* bih = role0 ? b_ih0 : b_ih1;
    const float* bhh = role0 ? b_hh0 : b_hh1;
    float* hbuf = role0 ? g_h1 : g_h2;

    // ---- prologue: zero h buffers (both parities, both layers) ----
    {
        int gid = cta * TPB + tid;
        for (int i = gid; i < 2 * HB; i += NCTA * TPB) { g_h1[i] = 0.0f; g_h2[i] = 0.0f; }
    }
    // ---- prologue: transpose X[b][t][d] -> g_xT[t][d][b] ; 4 timesteps per CTA ----
    for (int j = 0; j < 4; ++j) {
        int t = cta * 4 + j;
        for (int i = tid; i < Dsz * Bsz; i += TPB) {
            int d = i >> 6, b = i & 63;
            g_xT[(t * Dsz + d) * Bsz + b] = X[((size_t)b * Tsz + t) * Dsz + d];
        }
    }
    // ---- prologue: stage this CTA's weight slices into SMEM (resident all steps) ----
    for (int gu = 0; gu < 24; ++gu) {
        int u = gu / 3, g = gu % 3;
        int grow = g * Hsz + U0 + u;        // gate order r,z,n
        for (int k = tid; k < Hsz; k += TPB) WHs[k * 24 + gu] = Whh[(size_t)grow * Hsz + k];
        for (int k = tid; k < Kx;  k += TPB) WXs[k * 24 + gu] = Wih[(size_t)grow * Kx  + k];
    }
    // ---- prologue: per-thread bias registers for its 4 units ----
    float bsr[4], bsz[4], bxn[4], bhn[4];
#pragma unroll
    for (int u = 0; u < 4; ++u) {
        int uu = U0 + row * 4 + u;
        bsr[u] = bih[uu]            + bhh[uu];
        bsz[u] = bih[Hsz + uu]      + bhh[Hsz + uu];
        bxn[u] = bih[2 * Hsz + uu];
        bhn[u] = bhh[2 * Hsz + uu];
    }

    gridbar(1u, cta, tid);                  // xT + h-zero globally visible

    // ---- main pipelined recurrence: iter it computes L0 t=it and L1 t=it-1 ----
    for (int it = 0; it <= Tsz; ++it) {
        bool active = role0 ? (it < Tsz) : (it >= 1);
        if (active) {
            int pb = (it + 1) & 1, cb = it & 1;
            const float* hprev = hbuf + pb * HB;
            float*       hout  = hbuf + cb * HB;
            const float* xsrc  = role0 ? (g_xT + (size_t)it * Dsz * Bsz)
                                       : (g_h1 + pb * HB);

            ull aH[6] = {0,0,0,0,0,0};
            ull aX[6] = {0,0,0,0,0,0};

            // phase H: gh = W_hh . h_prev   (K = 512)
            for (int k0 = 0; k0 < Hsz; k0 += KC) {
                __syncthreads();
                copy_chunk(stage, hprev + (size_t)k0 * Bsz, tid);
                __syncthreads();
                accum_phase(WHs, stage, k0, col, gu_base, aH);
            }
            // phase X: gx = W_ih . x_t      (K = 128 or 512)
            for (int k0 = 0; k0 < Kx; k0 += KC) {
                __syncthreads();
                copy_chunk(stage, xsrc + (size_t)k0 * Bsz, tid);
                __syncthreads();
                accum_phase(WXs, stage, k0, col, gu_base, aX);
            }

            // combine: gates + state update for 4 units x 1 batch
            float gH[12], gX[12];
#pragma unroll
            for (int j = 0; j < 6; ++j) {
                unpack2(aH[j], gH[2 * j], gH[2 * j + 1]);
                unpack2(aX[j], gX[2 * j], gX[2 * j + 1]);
            }
#pragma unroll
            for (int u = 0; u < 4; ++u) {
                int i0 = u * 3;
                float r = sigmoidf_(gH[i0]     + gX[i0]     + bsr[u]);
                float z = sigmoidf_(gH[i0 + 1] + gX[i0 + 1] + bsz[u]);
                float n = tanhf_(gX[i0 + 2] + bxn[u] + r * (gH[i0 + 2] + bhn[u]));
                int uu = U0 + row * 4 + u;
                float hp = __ldcg(&hprev[uu * Bsz + col]);
                float hn = fmaf(z, hp - n, n);          // (1-z)*n + z*h
                __stcg(&hout[uu * Bsz + col], hn);
            }
        }
        gridbar(2u + (unsigned)it, cta, tid);
    }

    // ---- epilogue: FC on final h2 (written at it=512 into parity 0) ----
    if (cta == 0 && tid < Bsz) {
        const float* h2f = g_h2;            // buf 0
        float acc = b_fc[0];
#pragma unroll 8
        for (int u = 0; u < Hsz; ++u)
            acc = fmaf(W_fc[u], __ldcg(&h2f[u * Bsz + tid]), acc);
        out[tid] = acc;
    }

    // ---- reset barrier state so every graph replay starts clean ----
    __syncthreads();
    __threadfence();
    if (tid == 0) *((volatile unsigned*)&g_flags[cta]) = 0u;
    if (cta == 0) {
        volatile unsigned* f = &g_flags[tid];
        while (*f != 0u) __nanosleep(32);
        __syncthreads();
        if (tid == 0) {
            __threadfence();
            *((volatile unsigned*)&g_release) = 0u;
        }
    }
}

extern "C" void kernel_launch(void* const* d_in, const int* in_sizes, int n_in,
                              void* d_out, int out_size) {
    (void)in_sizes; (void)n_in; (void)out_size;
    const float* X     = (const float*)d_in[0];
    const float* W_ih0 = (const float*)d_in[1];
    const float* W_hh0 = (const float*)d_in[2];
    const float* b_ih0 = (const float*)d_in[3];
    const float* b_hh0 = (const float*)d_in[4];
    const float* W_ih1 = (const float*)d_in[5];
    const float* W_hh1 = (const float*)d_in[6];
    const float* b_ih1 = (const float*)d_in[7];
    const float* b_hh1 = (const float*)d_in[8];
    const float* W_fc  = (const float*)d_in[9];
    const float* b_fc  = (const float*)d_in[10];

    cudaFuncSetAttribute(gru_persistent,
                         cudaFuncAttributeMaxDynamicSharedMemorySize, SMEM_BYTES);
    gru_persistent<<<NCTA, TPB, SMEM_BYTES>>>(X, W_ih0, W_hh0, b_ih0, b_hh0,
                                              W_ih1, W_hh1, b_ih1, b_hh1,
                                              W_fc, b_fc, (float*)d_out);
}

// round 13
// speedup vs baseline: 1.5521x; 1.5521x over previous
#include <cuda_runtime.h>
#include <cstdint>

// ---------------- problem dims ----------------
#define Bsz   64
#define Tsz   512
#define Dsz   128
#define Hsz   512
#define HB    (Hsz * Bsz)        // 32768 floats per h buffer
#define NCTA  128
#define TPB   256
#define L0CTAS 64
#define KC    128                // k-chunk staged per inner pass
// WHs: 512*32 floats (64KB) | WXs: 512*32 (64KB) | stage: 2*KC*64 (64KB)
#define SMEM_FLOATS (512*32 + 512*32 + 2*KC*Bsz)
#define SMEM_BYTES  (SMEM_FLOATS * 4)            // 196608 B

typedef unsigned long long ull;

// ---------------- persistent device state ----------------
__device__ __align__(16) float g_xT[Tsz * Dsz * Bsz];   // X transposed to [t][d][b]
__device__ __align__(16) float g_h1[2 * HB];            // layer0 hidden, double buffered, [k][b]
__device__ __align__(16) float g_h2[2 * HB];            // layer1 hidden, double buffered, [k][b]
__device__ unsigned g_flags[NCTA];                      // zero-init; reset at kernel end
__device__ unsigned g_release;                          // zero-init; reset at kernel end

// packed f32x2 FMA: full fp32 rate (plain 3-reg FFMA is half rate on sm_103a)
#define FMA2(acc, w, x) asm("fma.rn.f32x2 %0, %1, %2, %0;" : "+l"(acc) : "l"(w), "l"(x))

__device__ __forceinline__ void unpack2(ull v, float& lo, float& hi) {
    asm("mov.b64 {%0, %1}, %2;" : "=f"(lo), "=f"(hi) : "l"(v));
}
__device__ __forceinline__ ull dup2(float h) {
    ull r; asm("mov.b64 %0, {%1, %1};" : "=l"(r) : "f"(h)); return r;
}
__device__ __forceinline__ float sigmoidf_(float x) {
    return __fdividef(1.0f, 1.0f + __expf(-x));
}
__device__ __forceinline__ float tanhf_(float x) {
    x = fminf(12.0f, fmaxf(-12.0f, x));
    float e = __expf(2.0f * x);
    return __fdividef(e - 1.0f, e + 1.0f);
}

__device__ __forceinline__ uint32_t smem_to_u32(const void* smem_ptr) {
    uint32_t addr;
    asm("{ .reg .u64 tmp; cvta.to.shared.u64 tmp, %1; cvt.u32.u64 %0, tmp; }"
        : "=r"(addr) : "l"(smem_ptr));
    return addr;
}

// cp.async: 16B global->shared via L2 (bypass L1: coherence point for cross-CTA h exchange)
__device__ __forceinline__ void cpasync16(uint32_t smem_dst, const float* gsrc) {
    asm volatile("cp.async.cg.shared.global [%0], [%1], 16;" :: "r"(smem_dst), "l"(gsrc));
}
__device__ __forceinline__ void cpasync_commit() {
    asm volatile("cp.async.commit_group;");
}
__device__ __forceinline__ void cpasync_wait0() {
    asm volatile("cp.async.wait_group 0;");
}

// ---------------- grid barrier: distributed flags + CTA0 aggregation ----------------
// All NCTA CTAs co-resident (128 <= 148 SMs). val strictly increases within a launch.
__device__ __forceinline__ void gridbar(unsigned val, int cta, int tid) {
    __syncthreads();
    if (tid == 0) {
        __threadfence();
        *((volatile unsigned*)&g_flags[cta]) = val;
    }
    if (cta == 0) {
        if (tid < NCTA) {
            volatile unsigned* f = &g_flags[tid];
            while (*f < val) __nanosleep(32);
        }
        __syncthreads();
        if (tid == 0) {
            __threadfence();
            *((volatile unsigned*)&g_release) = val;
        }
    }
    if (tid == 0) {
        volatile unsigned* r = &g_release;
        while (*r < val) __nanosleep(32);
        __threadfence();
    }
    __syncthreads();
}

// prefetch one KC x 64 chunk into stage buffer via cp.async (8 x 16B per thread)
__device__ __forceinline__ void prefetch_chunk(uint32_t stage_smem, const float* __restrict__ src,
                                               int tid) {
#pragma unroll
    for (int i = 0; i < (KC * Bsz) / (4 * TPB); ++i)       // 8 iters
        cpasync16(stage_smem + (tid + i * TPB) * 16, src + (tid + i * TPB) * 4);
    cpasync_commit();
}

// accumulate one KC chunk: thread owns 6 gate-rows (2 units) x 1 batch col -> 3 f32x2 accs
__device__ __forceinline__ void accum_chunk(const float* __restrict__ Wk,   // Wsh + k0*32
                                            const float* __restrict__ stage,
                                            int col, int rbase, ull acc[3]) {
#pragma unroll 8
    for (int kk = 0; kk < KC; ++kk) {
        ull hh = dup2(stage[kk * Bsz + col]);
        const float* wp = Wk + kk * 32 + rbase;            // 16B aligned (rbase = row*8)
        ulonglong2 w01 = *reinterpret_cast<const ulonglong2*>(wp);  // LDS.128 broadcast
        ull w2 = *reinterpret_cast<const ull*>(wp + 4);             // LDS.64 broadcast
        FMA2(acc[0], w01.x, hh);
        FMA2(acc[1], w01.y, hh);
        FMA2(acc[2], w2, hh);
    }
}

__global__ __launch_bounds__(TPB)
void gru_persistent(const float* __restrict__ X,
                    const float* __restrict__ W_ih0, const float* __restrict__ W_hh0,
                    const float* __restrict__ b_ih0, const float* __restrict__ b_hh0,
                    const float* __restrict__ W_ih1, const float* __restrict__ W_hh1,
                    const float* __restrict__ b_ih1, const float* __restrict__ b_hh1,
                    const float* __restrict__ W_fc,  const float* __restrict__ b_fc,
                    float* __restrict__ out) {
    extern __shared__ float smem[];
    float* WHs   = smem;                    // [512][32]  hh weights: k-row -> 4 groups of 8 (6 used)
    float* WXs   = smem + 512 * 32;         // [Kx][32]   ih weights, same layout
    float* stage = smem + 2 * 512 * 32;     // [2][KC][64] double-buffered chunk
    const uint32_t stage_smem = smem_to_u32(stage);

    const int tid = threadIdx.x;
    const int cta = blockIdx.x;
    const int col = tid & 63;               // batch index this thread owns
    const int row = tid >> 6;               // 0..3: unit-pair group
    const int rbase = row * 8;

    const bool role0 = (cta < L0CTAS);
    const int  lcta  = role0 ? cta : (cta - L0CTAS);
    const int  U0    = lcta * 8;            // global hidden-unit base for this CTA
    const int  Kx    = role0 ? Dsz : Hsz;
    const int  NCH   = 4 + Kx / KC;         // total chunks: 4 (H phase) + Kx/KC (X phase)

    const float* Whh = role0 ? W_hh0 : W_hh1;
    const float* Wih = role0 ? W_ih0 : W_ih1;
    const float* bih = role0 ? b_ih0 : b_ih1;
    const float* bhh = role0 ? b_hh0 : b_hh1;
    float* hbuf = role0 ? g_h1 : g_h2;

    // ---- prologue: zero h buffers ----
    {
        int gid = cta * TPB + tid;
        for (int i = gid; i < 2 * HB; i += NCTA * TPB) { g_h1[i] = 0.0f; g_h2[i] = 0.0f; }
    }
    // ---- prologue: transpose X[b][t][d] -> g_xT[t][d][b] ; 4 timesteps per CTA ----
    for (int j = 0; j < 4; ++j) {
        int t = cta * 4 + j;
        for (int i = tid; i < Dsz * Bsz; i += TPB) {
            int d = i >> 6, b = i & 63;
            g_xT[(t * Dsz + d) * Bsz + b] = X[((size_t)b * Tsz + t) * Dsz + d];
        }
    }
    // ---- prologue: stage this CTA's weight slices into SMEM ----
    // gu 0..23:  r = gu/6 (row group), lg = gu%6, unit = 2r + lg/3, gate g = lg%3
    for (int gu = 0; gu < 24; ++gu) {
        int r = gu / 6, lg = gu % 6;
        int unit = 2 * r + lg / 3, g = lg % 3;
        int grow = g * Hsz + U0 + unit;     // gate order r,z,n
        for (int k = tid; k < Hsz; k += TPB) WHs[k * 32 + r * 8 + lg] = Whh[(size_t)grow * Hsz + k];
        for (int k = tid; k < Kx;  k += TPB) WXs[k * 32 + r * 8 + lg] = Wih[(size_t)grow * Kx  + k];
    }
    // ---- prologue: per-thread bias registers for its 2 units ----
    float bsr[2], bsz_[2], bxn[2], bhn[2];
#pragma unroll
    for (int u = 0; u < 2; ++u) {
        int uu = U0 + row * 2 + u;
        bsr[u]  = bih[uu]           + bhh[uu];
        bsz_[u] = bih[Hsz + uu]     + bhh[Hsz + uu];
        bxn[u]  = bih[2 * Hsz + uu];
        bhn[u]  = bhh[2 * Hsz + uu];
    }

    gridbar(1u, cta, tid);                  // xT + h-zero globally visible

    // ---- main pipelined recurrence: iter it computes L0 t=it and L1 t=it-1 ----
    for (int it = 0; it <= Tsz; ++it) {
        bool active = role0 ? (it < Tsz) : (it >= 1);
        if (active) {
            int pb = (it + 1) & 1, cb = it & 1;
            const float* hprev = hbuf + pb * HB;
            float*       hout  = hbuf + cb * HB;
            const float* xsrc  = role0 ? (g_xT + (size_t)it * Dsz * Bsz)
                                       : (g_h1 + pb * HB);

            ull aH[3] = {0, 0, 0};
            ull aX[3] = {0, 0, 0};

            // chunk c: c<4 -> H phase (hprev, WHs), else X phase (xsrc, WXs)
            prefetch_chunk(stage_smem, hprev, tid);              // chunk 0 -> buf 0
            for (int c = 0; c < NCH; ++c) {
                cpasync_wait0();                                 // chunk c copy landed
                __syncthreads();                                 // visible to all; prev buf free
                if (c + 1 < NCH) {
                    const float* nsrc = (c + 1 < 4)
                        ? (hprev + (size_t)(c + 1) * KC * Bsz)
                        : (xsrc  + (size_t)(c + 1 - 4) * KC * Bsz);
                    prefetch_chunk(stage_smem + ((c + 1) & 1) * KC * Bsz * 4, nsrc, tid);
                }
                const float* stg = stage + (c & 1) * KC * Bsz;
                if (c < 4) accum_chunk(WHs + (size_t)c * KC * 32, stg, col, rbase, aH);
                else       accum_chunk(WXs + (size_t)(c - 4) * KC * 32, stg, col, rbase, aX);
            }

            // combine: gates + state update for 2 units x 1 batch col
            float gH[6], gX[6];
#pragma unroll
            for (int j = 0; j < 3; ++j) {
                unpack2(aH[j], gH[2 * j], gH[2 * j + 1]);
                unpack2(aX[j], gX[2 * j], gX[2 * j + 1]);
            }
#pragma unroll
            for (int u = 0; u < 2; ++u) {
                int i0 = u * 3;
                float r = sigmoidf_(gH[i0]     + gX[i0]     + bsr[u]);
                float z = sigmoidf_(gH[i0 + 1] + gX[i0 + 1] + bsz_[u]);
                float n = tanhf_(gX[i0 + 2] + bxn[u] + r * (gH[i0 + 2] + bhn[u]));
                int uu = U0 + row * 2 + u;
                float hp = __ldcg(&hprev[uu * Bsz + col]);
                float hn = fmaf(z, hp - n, n);          // (1-z)*n + z*h
                __stcg(&hout[uu * Bsz + col], hn);
            }
        }
        gridbar(2u + (unsigned)it, cta, tid);
    }

    // ---- epilogue: FC on final h2 (t=511 written at it=512 into parity 0) ----
    if (cta == 0 && tid < Bsz) {
        const float* h2f = g_h2;            // parity 0
        float acc = b_fc[0];
#pragma unroll 8
        for (int u = 0; u < Hsz; ++u)
            acc = fmaf(W_fc[u], __ldcg(&h2f[u * Bsz + tid]), acc);
        out[tid] = acc;
    }

    // ---- reset barrier state so every graph replay starts clean ----
    __syncthreads();
    __threadfence();
    if (tid == 0) *((volatile unsigned*)&g_flags[cta]) = 0u;
    if (cta == 0) {
        if (tid < NCTA) {
            volatile unsigned* f = &g_flags[tid];
            while (*f != 0u) __nanosleep(32);
        }
        __syncthreads();
        if (tid == 0) {
            __threadfence();
            *((volatile unsigned*)&g_release) = 0u;
        }
    }
}

extern "C" void kernel_launch(void* const* d_in, const int* in_sizes, int n_in,
                              void* d_out, int out_size) {
    (void)in_sizes; (void)n_in; (void)out_size;
    const float* X     = (const float*)d_in[0];
    const float* W_ih0 = (const float*)d_in[1];
    const float* W_hh0 = (const float*)d_in[2];
    const float* b_ih0 = (const float*)d_in[3];
    const float* b_hh0 = (const float*)d_in[4];
    const float* W_ih1 = (const float*)d_in[5];
    const float* W_hh1 = (const float*)d_in[6];
    const float* b_ih1 = (const float*)d_in[7];
    const float* b_hh1 = (const float*)d_in[8];
    const float* W_fc  = (const float*)d_in[9];
    const float* b_fc  = (const float*)d_in[10];

    cudaFuncSetAttribute(gru_persistent,
                         cudaFuncAttributeMaxDynamicSharedMemorySize, SMEM_BYTES);
    gru_persistent<<<NCTA, TPB, SMEM_BYTES>>>(X, W_ih0, W_hh0, b_ih0, b_hh0,
                                              W_ih1, W_hh1, b_ih1, b_hh1,
                                              W_fc, b_fc, (float*)d_out);
}